// round 1
// baseline (speedup 1.0000x reference)
#include <cuda_runtime.h>
#include <math.h>

#define NN 10000
#define EE 160000
#define FULLMASK 0xffffffffu

// ---------------- device scratch ----------------
__device__ float g_A0[NN * 64];
__device__ float g_B0[NN * 32];
__device__ float g_C1a[NN * 192];
__device__ float g_C1b[NN * 96];
__device__ float g_logit[EE];   // indexed by CSR position
__device__ float g_gate[EE];    // indexed by CSR position
__device__ int   g_cnt[NN];
__device__ int   g_cur[NN];
__device__ int   g_off[NN + 1];
__device__ int   g_perm[EE];
__device__ float g_Wfa[64 * 64];
__device__ float g_Wfb[64 * 32];
__device__ float g_Wga[32 * 64];
__device__ float g_Wgb[32 * 32];

// ---------------- helpers ----------------
__global__ void k_zero() {
    int i = blockIdx.x * blockDim.x + threadIdx.x;
    if (i < NN) { g_cnt[i] = 0; g_cur[i] = 0; }
}

// fuse Wq/Wd matrices with all normalization constants
__global__ void k_fusew(const float* __restrict__ Wq0, const float* __restrict__ Wq1,
                        const float* __restrict__ Wd00a, const float* __restrict__ Wd00b,
                        const float* __restrict__ Wd11a, const float* __restrict__ Wd11b) {
    const float SQRT3 = 1.7320508075688772f;
    const float SC_A  = 1.0f / (8.0f * 64.0f);
    const float SC_B  = 1.0f / (8.0f * sqrtf(2048.0f) * SQRT3);
    const float SC_GA = 1.0f / (sqrtf(32.0f) * SQRT3 * sqrtf(2048.0f));
    const float SC_GB = 1.0f / (sqrtf(32.0f) * SQRT3 * 32.0f);
    int tid = threadIdx.x;
    for (int o = tid; o < 64 * 64; o += blockDim.x) {
        int i = o >> 6, v = o & 63;
        float s = 0.f;
        for (int u = 0; u < 64; u++) s += Wq0[i * 64 + u] * Wd00a[u * 64 + v];
        g_Wfa[o] = s * SC_A;
    }
    for (int o = tid; o < 64 * 32; o += blockDim.x) {
        int i = o >> 5, v = o & 31;
        float s = 0.f;
        for (int u = 0; u < 64; u++) s += Wq0[i * 64 + u] * Wd00b[u * 32 + v];
        g_Wfb[o] = s * SC_B;
    }
    for (int o = tid; o < 32 * 64; o += blockDim.x) {
        int t = o >> 6, v = o & 63;
        float s = 0.f;
        for (int u = 0; u < 32; u++) s += Wq1[t * 32 + u] * Wd11a[u * 64 + v];
        g_Wga[o] = s * SC_GA;
    }
    for (int o = tid; o < 32 * 32; o += blockDim.x) {
        int t = o >> 5, v = o & 31;
        float s = 0.f;
        for (int u = 0; u < 32; u++) s += Wq1[t * 32 + u] * Wd11b[u * 32 + v];
        g_Wgb[o] = s * SC_GB;
    }
}

// per-node precompute: A0 = s@Wfa, B0 = s@Wfb, C1a[:,v,m] = v[:,:,m]@Wga, C1b = v@Wgb
__global__ __launch_bounds__(256) void k_node(const float* __restrict__ f) {
    extern __shared__ float sm[];
    float* sWfa = sm;            // 4096
    float* sWfb = sm + 4096;     // 2048
    float* sWga = sm + 6144;     // 2048
    float* sWgb = sm + 8192;     // 1024
    int tid = threadIdx.x;
    for (int i = tid; i < 4096; i += 256) sWfa[i] = g_Wfa[i];
    for (int i = tid; i < 2048; i += 256) sWfb[i] = g_Wfb[i];
    for (int i = tid; i < 2048; i += 256) sWga[i] = g_Wga[i];
    for (int i = tid; i < 1024; i += 256) sWgb[i] = g_Wgb[i];
    __syncthreads();
    int w = tid >> 5, lane = tid & 31;
    int n = blockIdx.x * 8 + w;
    if (n >= NN) return;
    const float* fn = f + (size_t)n * 160;
    float s0 = fn[lane], s1 = fn[32 + lane];
    float v0 = fn[64 + 3 * lane], v1 = fn[65 + 3 * lane], v2 = fn[66 + 3 * lane];
    float a0 = 0.f, a0b = 0.f, b0 = 0.f;
    float ca[3] = {0.f, 0.f, 0.f}, ca2[3] = {0.f, 0.f, 0.f}, cb[3] = {0.f, 0.f, 0.f};
#pragma unroll
    for (int i = 0; i < 32; i++) {
        float si = __shfl_sync(FULLMASK, s0, i);
        a0  = fmaf(si, sWfa[i * 64 + lane], a0);
        a0b = fmaf(si, sWfa[i * 64 + 32 + lane], a0b);
        b0  = fmaf(si, sWfb[i * 32 + lane], b0);
    }
#pragma unroll
    for (int i = 0; i < 32; i++) {
        float si = __shfl_sync(FULLMASK, s1, i);
        a0  = fmaf(si, sWfa[(32 + i) * 64 + lane], a0);
        a0b = fmaf(si, sWfa[(32 + i) * 64 + 32 + lane], a0b);
        b0  = fmaf(si, sWfb[(32 + i) * 32 + lane], b0);
    }
#pragma unroll
    for (int t = 0; t < 32; t++) {
        float t0 = __shfl_sync(FULLMASK, v0, t);
        float t1 = __shfl_sync(FULLMASK, v1, t);
        float t2 = __shfl_sync(FULLMASK, v2, t);
        float wa  = sWga[t * 64 + lane];
        float wa2 = sWga[t * 64 + 32 + lane];
        float wb  = sWgb[t * 32 + lane];
        ca[0] = fmaf(t0, wa, ca[0]);  ca[1] = fmaf(t1, wa, ca[1]);  ca[2] = fmaf(t2, wa, ca[2]);
        ca2[0] = fmaf(t0, wa2, ca2[0]); ca2[1] = fmaf(t1, wa2, ca2[1]); ca2[2] = fmaf(t2, wa2, ca2[2]);
        cb[0] = fmaf(t0, wb, cb[0]);  cb[1] = fmaf(t1, wb, cb[1]);  cb[2] = fmaf(t2, wb, cb[2]);
    }
    g_A0[(size_t)n * 64 + lane] = a0;
    g_A0[(size_t)n * 64 + 32 + lane] = a0b;
    g_B0[(size_t)n * 32 + lane] = b0;
#pragma unroll
    for (int m = 0; m < 3; m++) {
        g_C1a[(size_t)n * 192 + 3 * lane + m] = ca[m];
        g_C1a[(size_t)n * 192 + 3 * (lane + 32) + m] = ca2[m];
        g_C1b[(size_t)n * 96 + 3 * lane + m] = cb[m];
    }
}

__global__ void k_count(const int* __restrict__ edst) {
    int e = blockIdx.x * blockDim.x + threadIdx.x;
    if (e < EE) atomicAdd(&g_cnt[edst[e]], 1);
}

__global__ void k_scan() {
    __shared__ int sp[1024];
    int t = threadIdx.x;
    int sum = 0;
    if (t < 1000) {
        for (int k = 0; k < 10; k++) sum += g_cnt[t * 10 + k];
    }
    sp[t] = sum;
    __syncthreads();
    for (int off = 1; off < 1024; off <<= 1) {
        int v = (t >= off) ? sp[t - off] : 0;
        __syncthreads();
        sp[t] += v;
        __syncthreads();
    }
    int excl = (t == 0) ? 0 : sp[t - 1];
    if (t < 1000) {
        int run = excl;
        for (int k = 0; k < 10; k++) {
            g_off[t * 10 + k] = run;
            run += g_cnt[t * 10 + k];
        }
    }
    if (t == 0) g_off[NN] = EE;
}

__global__ void k_scatter(const int* __restrict__ edst) {
    int e = blockIdx.x * blockDim.x + threadIdx.x;
    if (e < EE) {
        int d = edst[e];
        int r = atomicAdd(&g_cur[d], 1);
        g_perm[g_off[d] + r] = e;
    }
}

// warp-collective 16->64(silu)->192 MLP; lane ends with wk[c] = out[c*32+lane]
__device__ __forceinline__ void edge_mlp(const float* __restrict__ sW1,
                                         const float* __restrict__ sW2,
                                         const float* __restrict__ x16,
                                         int lane, float wk[6]) {
    float xv = (lane < 16) ? x16[lane] : 0.f;
    float h0 = 0.f, h1 = 0.f;
#pragma unroll
    for (int i = 0; i < 16; i++) {
        float xi = __shfl_sync(FULLMASK, xv, i);
        h0 = fmaf(xi, sW1[i * 64 + lane], h0);
        h1 = fmaf(xi, sW1[i * 64 + 32 + lane], h1);
    }
    h0 *= 0.25f; h1 *= 0.25f;
    h0 = h0 / (1.f + expf(-h0));
    h1 = h1 / (1.f + expf(-h1));
#pragma unroll
    for (int c = 0; c < 6; c++) wk[c] = 0.f;
#pragma unroll
    for (int k = 0; k < 32; k++) {
        float hk = __shfl_sync(FULLMASK, h0, k);
        const float* w = &sW2[k * 192 + lane];
#pragma unroll
        for (int c = 0; c < 6; c++) wk[c] = fmaf(hk, w[c * 32], wk[c]);
    }
#pragma unroll
    for (int k = 0; k < 32; k++) {
        float hk = __shfl_sync(FULLMASK, h1, k);
        const float* w = &sW2[(32 + k) * 192 + lane];
#pragma unroll
        for (int c = 0; c < 6; c++) wk[c] = fmaf(hk, w[c * 32], wk[c]);
    }
#pragma unroll
    for (int c = 0; c < 6; c++) wk[c] *= 0.125f;
}

// node-parallel: logits, per-node softmax, gate
__global__ __launch_bounds__(256) void k_logits(const float* __restrict__ f,
                                                const int* __restrict__ esrc,
                                                const float* __restrict__ esh,
                                                const float* __restrict__ elen,
                                                const float* __restrict__ ecut,
                                                const float* __restrict__ Wk1,
                                                const float* __restrict__ Wk2) {
    extern __shared__ float sm[];
    float* sW1  = sm;                 // 1024
    float* sW2  = sm + 1024;          // 12288
    float* sDst = sm + 1024 + 12288;  // 384
    float* sRed = sDst + 384;         // 16
    int tid = threadIdx.x;
    for (int i = tid; i < 1024; i += 256) sW1[i] = Wk1[i];
    for (int i = tid; i < 12288; i += 256) sW2[i] = Wk2[i];
    int w = tid >> 5, lane = tid & 31;
    for (int node = blockIdx.x; node < NN; node += gridDim.x) {
        __syncthreads();
        for (int i = tid; i < 384; i += 256) {
            float v;
            if (i < 64)       v = g_A0[(size_t)node * 64 + i];
            else if (i < 96)  v = g_B0[(size_t)node * 32 + (i - 64)];
            else if (i < 288) v = g_C1a[(size_t)node * 192 + (i - 96)];
            else              v = g_C1b[(size_t)node * 96 + (i - 288)];
            sDst[i] = v;
        }
        __syncthreads();
        int beg = g_off[node];
        int cnt = g_off[node + 1] - beg;
        float wmax = -INFINITY;
        for (int idx = w; idx < cnt; idx += 8) {
            int e = g_perm[beg + idx];
            int src = esrc[e];
            float wk[6];
            edge_mlp(sW1, sW2, elen + (size_t)e * 16, lane, wk);
            const float* fs = f + (size_t)src * 160;
            float ss0 = fs[lane], ss1 = fs[32 + lane];
            float vs0 = fs[64 + 3 * lane], vs1 = fs[65 + 3 * lane], vs2 = fs[66 + 3 * lane];
            float yv = (lane < 4) ? esh[(size_t)e * 4 + lane] : 0.f;
            float y0  = __shfl_sync(FULLMASK, yv, 0);
            float y1x = __shfl_sync(FULLMASK, yv, 1);
            float y1y = __shfl_sync(FULLMASK, yv, 2);
            float y1z = __shfl_sync(FULLMASK, yv, 3);
            float A0a = sDst[lane], A0b = sDst[32 + lane], B0v = sDst[64 + lane];
            float ca0 = sDst[96 + 3 * lane], ca1 = sDst[97 + 3 * lane], ca2v = sDst[98 + 3 * lane];
            float cb0 = sDst[192 + 3 * lane], cb1 = sDst[193 + 3 * lane], cb2 = sDst[194 + 3 * lane];
            float d0 = sDst[288 + 3 * lane], d1 = sDst[289 + 3 * lane], d2 = sDst[290 + 3 * lane];
            float t = y0 * (wk[0] * ss0 * A0a + wk[1] * ss1 * A0b)
                    + wk[2] * ss0 * (ca0 * y1x + ca1 * y1y + ca2v * y1z)
                    + wk[3] * ss1 * (cb0 * y1x + cb1 * y1y + cb2 * y1z)
                    + y0 * wk[4] * (vs0 * d0 + vs1 * d1 + vs2 * d2)
                    + wk[5] * B0v * (vs0 * y1x + vs1 * y1y + vs2 * y1z);
#pragma unroll
            for (int o = 16; o > 0; o >>= 1) t += __shfl_xor_sync(FULLMASK, t, o);
            if (lane == 0) g_logit[beg + idx] = t;
            wmax = fmaxf(wmax, t);
        }
        if (lane == 0) sRed[w] = wmax;
        __syncthreads();
        if (tid == 0) {
            float m = sRed[0];
            for (int i = 1; i < 8; i++) m = fmaxf(m, sRed[i]);
            sRed[8] = m;
        }
        __syncthreads();
        float m = sRed[8];
        float zsum = 0.f;
        for (int idx = tid; idx < cnt; idx += 256) zsum += expf(g_logit[beg + idx] - m);
#pragma unroll
        for (int o = 16; o > 0; o >>= 1) zsum += __shfl_xor_sync(FULLMASK, zsum, o);
        if (lane == 0) sRed[w] = zsum;
        __syncthreads();
        if (tid == 0) {
            float den = 0.f;
            for (int i = 0; i < 8; i++) den += sRed[i];
            sRed[9] = den;
        }
        __syncthreads();
        float den = sRed[9];
        for (int idx = tid; idx < cnt; idx += 256) {
            int e = g_perm[beg + idx];
            float z = expf(g_logit[beg + idx] - m);
            float alpha = z / den * ecut[e];
            g_gate[beg + idx] = sqrtf(fmaxf(alpha, 0.f) + 1e-12f);
        }
    }
}

// node-parallel output accumulation
__global__ __launch_bounds__(256) void k_out(const float* __restrict__ f,
                                             const int* __restrict__ esrc,
                                             const float* __restrict__ esh,
                                             const float* __restrict__ elen,
                                             const float* __restrict__ Wv1,
                                             const float* __restrict__ Wv2,
                                             float* __restrict__ out) {
    extern __shared__ float sm[];
    float* sW1   = sm;                // 1024
    float* sW2   = sm + 1024;         // 12288
    float* sPart = sm + 1024 + 12288; // 8*384 = 3072
    const float RSQRT3 = 0.5773502691896258f;
    int tid = threadIdx.x;
    for (int i = tid; i < 1024; i += 256) sW1[i] = Wv1[i];
    for (int i = tid; i < 12288; i += 256) sW2[i] = Wv2[i];
    int w = tid >> 5, lane = tid & 31;
    for (int node = blockIdx.x; node < NN; node += gridDim.x) {
        __syncthreads();
        int beg = g_off[node];
        int cnt = g_off[node + 1] - beg;
        float acc[12];
#pragma unroll
        for (int i = 0; i < 12; i++) acc[i] = 0.f;
        for (int idx = w; idx < cnt; idx += 8) {
            int e = g_perm[beg + idx];
            int src = esrc[e];
            float wv[6];
            edge_mlp(sW1, sW2, elen + (size_t)e * 16, lane, wv);
            const float* fs = f + (size_t)src * 160;
            float ss0 = fs[lane], ss1 = fs[32 + lane];
            float vs0 = fs[64 + 3 * lane], vs1 = fs[65 + 3 * lane], vs2 = fs[66 + 3 * lane];
            float yv = (lane < 4) ? esh[(size_t)e * 4 + lane] : 0.f;
            float y0  = __shfl_sync(FULLMASK, yv, 0);
            float y1x = __shfl_sync(FULLMASK, yv, 1);
            float y1y = __shfl_sync(FULLMASK, yv, 2);
            float y1z = __shfl_sync(FULLMASK, yv, 3);
            float gate = g_gate[beg + idx];
            float gy0 = gate * y0;
            acc[0] = fmaf(gy0 * wv[0], ss0, acc[0]);
            acc[1] = fmaf(gy0 * wv[1], ss1, acc[1]);
            acc[2] = fmaf(gate * wv[5] * RSQRT3, vs0 * y1x + vs1 * y1y + vs2 * y1z, acc[2]);
            float a1 = gate * wv[2] * ss0;
            acc[3] = fmaf(a1, y1x, acc[3]); acc[4] = fmaf(a1, y1y, acc[4]); acc[5] = fmaf(a1, y1z, acc[5]);
            float a2 = gate * wv[3] * ss1;
            acc[6] = fmaf(a2, y1x, acc[6]); acc[7] = fmaf(a2, y1y, acc[7]); acc[8] = fmaf(a2, y1z, acc[8]);
            float a3 = gy0 * wv[4];
            acc[9] = fmaf(a3, vs0, acc[9]); acc[10] = fmaf(a3, vs1, acc[10]); acc[11] = fmaf(a3, vs2, acc[11]);
        }
        float* sp = sPart + w * 384;
        sp[lane] = acc[0];
        sp[32 + lane] = acc[1];
        sp[64 + lane] = acc[2];
        sp[96 + 3 * lane] = acc[3];  sp[97 + 3 * lane] = acc[4];  sp[98 + 3 * lane] = acc[5];
        sp[192 + 3 * lane] = acc[6]; sp[193 + 3 * lane] = acc[7]; sp[194 + 3 * lane] = acc[8];
        sp[288 + 3 * lane] = acc[9]; sp[289 + 3 * lane] = acc[10]; sp[290 + 3 * lane] = acc[11];
        __syncthreads();
        for (int ch = tid; ch < 384; ch += 256) {
            float s = 0.f;
#pragma unroll
            for (int ww = 0; ww < 8; ww++) s += sPart[ww * 384 + ch];
            out[(size_t)node * 384 + ch] = s;
        }
    }
}

// ---------------- launch ----------------
extern "C" void kernel_launch(void* const* d_in, const int* in_sizes, int n_in,
                              void* d_out, int out_size) {
    const float* f    = (const float*)d_in[0];
    const int*   esrc = (const int*)d_in[3];
    const int*   edst = (const int*)d_in[4];
    const float* esh  = (const float*)d_in[5];
    const float* elen = (const float*)d_in[6];
    const float* ecut = (const float*)d_in[7];
    const float* Wq0  = (const float*)d_in[8];
    const float* Wq1  = (const float*)d_in[9];
    const float* Wk1  = (const float*)d_in[10];
    const float* Wk2  = (const float*)d_in[11];
    const float* Wv1  = (const float*)d_in[12];
    const float* Wv2  = (const float*)d_in[13];
    const float* Wd00a = (const float*)d_in[14];
    const float* Wd00b = (const float*)d_in[15];
    const float* Wd11a = (const float*)d_in[16];
    const float* Wd11b = (const float*)d_in[17];
    float* out = (float*)d_out;

    const int SM_NODE = 9216 * sizeof(float);
    const int SM_LG   = (1024 + 12288 + 384 + 16) * sizeof(float);
    const int SM_OUT  = (1024 + 12288 + 3072) * sizeof(float);
    cudaFuncSetAttribute(k_logits, cudaFuncAttributeMaxDynamicSharedMemorySize, SM_LG);
    cudaFuncSetAttribute(k_out, cudaFuncAttributeMaxDynamicSharedMemorySize, SM_OUT);

    k_zero<<<(NN + 255) / 256, 256>>>();
    k_fusew<<<1, 256>>>(Wq0, Wq1, Wd00a, Wd00b, Wd11a, Wd11b);
    k_node<<<(NN + 7) / 8, 256, SM_NODE>>>(f);
    k_count<<<(EE + 255) / 256, 256>>>(edst);
    k_scan<<<1, 1024>>>();
    k_scatter<<<(EE + 255) / 256, 256>>>(edst);
    k_logits<<<1024, 256, SM_LG>>>(f, esrc, esh, elen, ecut, Wk1, Wk2);
    k_out<<<1024, 256, SM_OUT>>>(f, esrc, esh, elen, Wv1, Wv2, out);
}

// round 2
// speedup vs baseline: 1.7557x; 1.7557x over previous
#include <cuda_runtime.h>
#include <math.h>

#define NN 10000
#define EE 160000
#define FULLMASK 0xffffffffu

// fma.rn.f32x2: packed 2xfp32 FMA (Blackwell) — d = a*b + d elementwise on pairs
#define FMA2(d, a, b) asm("fma.rn.f32x2 %0, %1, %2, %0;" : "+l"(d) : "l"(a), "l"(b))

// ---------------- device scratch ----------------
__device__ float g_A0[NN * 64];
__device__ float g_B0[NN * 32];
__device__ float g_C1a[NN * 192];
__device__ float g_C1b[NN * 96];
__device__ float g_logit_e[EE];          // edge-indexed logits
__device__ int   g_cnt[NN];
__device__ int   g_cur[NN];
__device__ int   g_off[NN + 1];
__device__ int   g_perm[EE];
__device__ float g_Wfa[64 * 64];
__device__ float g_Wfb[64 * 32];
__device__ float g_Wga[32 * 64];
__device__ float g_Wgb[32 * 32];
__device__ float g_WK[(size_t)EE * 192]; // edge MLP outputs (key path)
__device__ float g_WV[(size_t)EE * 192]; // edge MLP outputs (value path)

// ---------------- small setup kernels ----------------
__global__ void k_zero() {
    int i = blockIdx.x * blockDim.x + threadIdx.x;
    if (i < NN) { g_cnt[i] = 0; g_cur[i] = 0; }
}

__global__ void k_fusew(const float* __restrict__ Wq0, const float* __restrict__ Wq1,
                        const float* __restrict__ Wd00a, const float* __restrict__ Wd00b,
                        const float* __restrict__ Wd11a, const float* __restrict__ Wd11b) {
    const float SQRT3 = 1.7320508075688772f;
    const float SC_A  = 1.0f / (8.0f * 64.0f);
    const float SC_B  = 1.0f / (8.0f * sqrtf(2048.0f) * SQRT3);
    const float SC_GA = 1.0f / (sqrtf(32.0f) * SQRT3 * sqrtf(2048.0f));
    const float SC_GB = 1.0f / (sqrtf(32.0f) * SQRT3 * 32.0f);
    int tid = threadIdx.x;
    for (int o = tid; o < 64 * 64; o += blockDim.x) {
        int i = o >> 6, v = o & 63;
        float s = 0.f;
        for (int u = 0; u < 64; u++) s += Wq0[i * 64 + u] * Wd00a[u * 64 + v];
        g_Wfa[o] = s * SC_A;
    }
    for (int o = tid; o < 64 * 32; o += blockDim.x) {
        int i = o >> 5, v = o & 31;
        float s = 0.f;
        for (int u = 0; u < 64; u++) s += Wq0[i * 64 + u] * Wd00b[u * 32 + v];
        g_Wfb[o] = s * SC_B;
    }
    for (int o = tid; o < 32 * 64; o += blockDim.x) {
        int t = o >> 6, v = o & 63;
        float s = 0.f;
        for (int u = 0; u < 32; u++) s += Wq1[t * 32 + u] * Wd11a[u * 64 + v];
        g_Wga[o] = s * SC_GA;
    }
    for (int o = tid; o < 32 * 32; o += blockDim.x) {
        int t = o >> 5, v = o & 31;
        float s = 0.f;
        for (int u = 0; u < 32; u++) s += Wq1[t * 32 + u] * Wd11b[u * 32 + v];
        g_Wgb[o] = s * SC_GB;
    }
}

// per-node precompute: A0 = s@Wfa, B0 = s@Wfb, C1a = v@Wga, C1b = v@Wgb
__global__ __launch_bounds__(256) void k_node(const float* __restrict__ f) {
    extern __shared__ float sm[];
    float* sWfa = sm;
    float* sWfb = sm + 4096;
    float* sWga = sm + 6144;
    float* sWgb = sm + 8192;
    int tid = threadIdx.x;
    for (int i = tid; i < 4096; i += 256) sWfa[i] = g_Wfa[i];
    for (int i = tid; i < 2048; i += 256) sWfb[i] = g_Wfb[i];
    for (int i = tid; i < 2048; i += 256) sWga[i] = g_Wga[i];
    for (int i = tid; i < 1024; i += 256) sWgb[i] = g_Wgb[i];
    __syncthreads();
    int w = tid >> 5, lane = tid & 31;
    int n = blockIdx.x * 8 + w;
    if (n >= NN) return;
    const float* fn = f + (size_t)n * 160;
    float s0 = fn[lane], s1 = fn[32 + lane];
    float v0 = fn[64 + 3 * lane], v1 = fn[65 + 3 * lane], v2 = fn[66 + 3 * lane];
    float a0 = 0.f, a0b = 0.f, b0 = 0.f;
    float ca[3] = {0.f, 0.f, 0.f}, ca2[3] = {0.f, 0.f, 0.f}, cb[3] = {0.f, 0.f, 0.f};
#pragma unroll
    for (int i = 0; i < 32; i++) {
        float si = __shfl_sync(FULLMASK, s0, i);
        a0  = fmaf(si, sWfa[i * 64 + lane], a0);
        a0b = fmaf(si, sWfa[i * 64 + 32 + lane], a0b);
        b0  = fmaf(si, sWfb[i * 32 + lane], b0);
    }
#pragma unroll
    for (int i = 0; i < 32; i++) {
        float si = __shfl_sync(FULLMASK, s1, i);
        a0  = fmaf(si, sWfa[(32 + i) * 64 + lane], a0);
        a0b = fmaf(si, sWfa[(32 + i) * 64 + 32 + lane], a0b);
        b0  = fmaf(si, sWfb[(32 + i) * 32 + lane], b0);
    }
#pragma unroll
    for (int t = 0; t < 32; t++) {
        float t0 = __shfl_sync(FULLMASK, v0, t);
        float t1 = __shfl_sync(FULLMASK, v1, t);
        float t2 = __shfl_sync(FULLMASK, v2, t);
        float wa  = sWga[t * 64 + lane];
        float wa2 = sWga[t * 64 + 32 + lane];
        float wb  = sWgb[t * 32 + lane];
        ca[0] = fmaf(t0, wa, ca[0]);  ca[1] = fmaf(t1, wa, ca[1]);  ca[2] = fmaf(t2, wa, ca[2]);
        ca2[0] = fmaf(t0, wa2, ca2[0]); ca2[1] = fmaf(t1, wa2, ca2[1]); ca2[2] = fmaf(t2, wa2, ca2[2]);
        cb[0] = fmaf(t0, wb, cb[0]);  cb[1] = fmaf(t1, wb, cb[1]);  cb[2] = fmaf(t2, wb, cb[2]);
    }
    g_A0[(size_t)n * 64 + lane] = a0;
    g_A0[(size_t)n * 64 + 32 + lane] = a0b;
    g_B0[(size_t)n * 32 + lane] = b0;
#pragma unroll
    for (int m = 0; m < 3; m++) {
        g_C1a[(size_t)n * 192 + 3 * lane + m] = ca[m];
        g_C1a[(size_t)n * 192 + 3 * (lane + 32) + m] = ca2[m];
        g_C1b[(size_t)n * 96 + 3 * lane + m] = cb[m];
    }
}

__global__ void k_count(const int* __restrict__ edst) {
    int e = blockIdx.x * blockDim.x + threadIdx.x;
    if (e < EE) atomicAdd(&g_cnt[edst[e]], 1);
}

__global__ void k_scan() {
    __shared__ int sp[1024];
    int t = threadIdx.x;
    int sum = 0;
    if (t < 1000) for (int k = 0; k < 10; k++) sum += g_cnt[t * 10 + k];
    sp[t] = sum;
    __syncthreads();
    for (int off = 1; off < 1024; off <<= 1) {
        int v = (t >= off) ? sp[t - off] : 0;
        __syncthreads();
        sp[t] += v;
        __syncthreads();
    }
    int excl = (t == 0) ? 0 : sp[t - 1];
    if (t < 1000) {
        int run = excl;
        for (int k = 0; k < 10; k++) { g_off[t * 10 + k] = run; run += g_cnt[t * 10 + k]; }
    }
    if (t == 0) g_off[NN] = EE;
}

__global__ void k_scatter(const int* __restrict__ edst) {
    int e = blockIdx.x * blockDim.x + threadIdx.x;
    if (e < EE) {
        int d = edst[e];
        int r = atomicAdd(&g_cur[d], 1);
        g_perm[g_off[d] + r] = e;
    }
}

// ---------------- edge MLP as persistent tiled GEMM (f32x2 packed) ----------------
// 16 -> 64 (silu) -> 192, for both K and V weight sets. Output: g_WK / g_WV, [E][192].
// Tile: 64 edges. Block 256 threads. Weights resident in smem per block.
__global__ __launch_bounds__(256, 2) void k_mlp(const float* __restrict__ elen,
                                                const float* __restrict__ Wk1,
                                                const float* __restrict__ Wk2,
                                                const float* __restrict__ Wv1,
                                                const float* __restrict__ Wv2) {
    extern __shared__ float sm[];
    float*  sW1 = sm;                    // 1024
    float*  sW2 = sm + 1024;             // 12288
    float2* sH  = (float2*)(sm + 1024 + 12288);   // 64k x 64e duplicated pairs (8192 floats)
    float*  sX  = sm + 1024 + 12288 + 8192;       // 64 x 17 padded (1088 floats)
    int tid = threadIdx.x;

    int half = gridDim.x >> 1;
    bool isV = blockIdx.x >= half;
    const float* W1 = isV ? Wv1 : Wk1;
    const float* W2 = isV ? Wv2 : Wk2;
    float* OUT = isV ? g_WV : g_WK;
    int b0 = isV ? (blockIdx.x - half) : blockIdx.x;

    for (int i = tid; i < 1024; i += 256) sW1[i] = W1[i] * 0.25f;   // fold /sqrt(16)
    for (int i = tid; i < 12288; i += 256) sW2[i] = W2[i];

    const int NTILES = EE / 64;  // 2500
    for (int tile = b0; tile < NTILES; tile += half) {
        __syncthreads();
        // load X tile: 64 edges x 16 feats = 1024 floats via float4
        {
            const float4* src = (const float4*)(elen + (size_t)tile * 64 * 16);
            float4 xv = src[tid];
            int le = tid >> 2, li = (tid & 3) * 4;
            float* xp = &sX[le * 17 + li];
            xp[0] = xv.x; xp[1] = xv.y; xp[2] = xv.z; xp[3] = xv.w;
        }
        __syncthreads();
        // stage 1: H = silu(X @ W1) * 0.125 (fold /sqrt(64)); store duplicated (h,h)
        {
            int e = tid & 63, jg = tid >> 6;   // jg in 0..3 -> cols jg*16..+15
            float h[16];
#pragma unroll
            for (int j = 0; j < 16; j++) h[j] = 0.f;
#pragma unroll
            for (int i = 0; i < 16; i++) {
                float x = sX[e * 17 + i];
                const float* w = &sW1[i * 64 + jg * 16];
#pragma unroll
                for (int j = 0; j < 16; j++) h[j] = fmaf(x, w[j], h[j]);
            }
#pragma unroll
            for (int j = 0; j < 16; j++) {
                float t = h[j];
                t = t / (1.f + expf(-t));
                t *= 0.125f;
                sH[(jg * 16 + j) * 64 + e] = make_float2(t, t);
            }
        }
        __syncthreads();
        // stage 2: OUT = H @ W2 via f32x2-packed register tile
        {
            int tx = tid & 31, ty = tid >> 5;    // tx: col-pair group; ty: edge group
            unsigned long long acc[8][3];
#pragma unroll
            for (int j = 0; j < 8; j++) { acc[j][0] = 0ull; acc[j][1] = 0ull; acc[j][2] = 0ull; }
            const unsigned long long* H64 = (const unsigned long long*)sH;
            const unsigned long long* W64 = (const unsigned long long*)sW2;
            for (int kk = 0; kk < 64; kk++) {
                unsigned long long bb0 = W64[kk * 96 + tx];
                unsigned long long bb1 = W64[kk * 96 + tx + 32];
                unsigned long long bb2 = W64[kk * 96 + tx + 64];
                const unsigned long long* hrow = &H64[kk * 64 + ty * 8];
#pragma unroll
                for (int j = 0; j < 8; j++) {
                    unsigned long long a = hrow[j];
                    FMA2(acc[j][0], a, bb0);
                    FMA2(acc[j][1], a, bb1);
                    FMA2(acc[j][2], a, bb2);
                }
            }
            float* outp = OUT + (size_t)tile * 64 * 192;
#pragma unroll
            for (int j = 0; j < 8; j++) {
                int ee = ty * 8 + j;
                float2* op = (float2*)(outp + (size_t)ee * 192);
                op[tx]      = *(float2*)&acc[j][0];
                op[tx + 32] = *(float2*)&acc[j][1];
                op[tx + 64] = *(float2*)&acc[j][2];
            }
        }
    }
}

// ---------------- logits: warp per edge, reads WK + gathered node data ----------------
__global__ __launch_bounds__(256) void k_logit(const float* __restrict__ f,
                                               const int* __restrict__ esrc,
                                               const int* __restrict__ edst,
                                               const float* __restrict__ esh) {
    int gw = (blockIdx.x * 256 + threadIdx.x) >> 5;
    int lane = threadIdx.x & 31;
    if (gw >= EE) return;
    int e = gw;
    float wk0 = g_WK[(size_t)e * 192 + lane];
    float wk1 = g_WK[(size_t)e * 192 + 32 + lane];
    float wk2 = g_WK[(size_t)e * 192 + 64 + lane];
    float wk3 = g_WK[(size_t)e * 192 + 96 + lane];
    float wk4 = g_WK[(size_t)e * 192 + 128 + lane];
    float wk5 = g_WK[(size_t)e * 192 + 160 + lane];
    int src = esrc[e], dst = edst[e];
    const float* fs = f + (size_t)src * 160;
    float ss0 = fs[lane], ss1 = fs[32 + lane];
    float vs0 = fs[64 + 3 * lane], vs1 = fs[65 + 3 * lane], vs2 = fs[66 + 3 * lane];
    float yv = (lane < 4) ? esh[(size_t)e * 4 + lane] : 0.f;
    float y0  = __shfl_sync(FULLMASK, yv, 0);
    float y1x = __shfl_sync(FULLMASK, yv, 1);
    float y1y = __shfl_sync(FULLMASK, yv, 2);
    float y1z = __shfl_sync(FULLMASK, yv, 3);
    float A0a = g_A0[(size_t)dst * 64 + lane];
    float A0b = g_A0[(size_t)dst * 64 + 32 + lane];
    float B0v = g_B0[(size_t)dst * 32 + lane];
    float ca0 = g_C1a[(size_t)dst * 192 + 3 * lane + 0];
    float ca1 = g_C1a[(size_t)dst * 192 + 3 * lane + 1];
    float ca2 = g_C1a[(size_t)dst * 192 + 3 * lane + 2];
    float cb0 = g_C1a[(size_t)dst * 192 + 3 * (lane + 32) + 0];
    float cb1 = g_C1a[(size_t)dst * 192 + 3 * (lane + 32) + 1];
    float cb2 = g_C1a[(size_t)dst * 192 + 3 * (lane + 32) + 2];
    float d0  = g_C1b[(size_t)dst * 96 + 3 * lane + 0];
    float d1  = g_C1b[(size_t)dst * 96 + 3 * lane + 1];
    float d2  = g_C1b[(size_t)dst * 96 + 3 * lane + 2];
    float t = y0 * (wk0 * ss0 * A0a + wk1 * ss1 * A0b)
            + wk2 * ss0 * (ca0 * y1x + ca1 * y1y + ca2 * y1z)
            + wk3 * ss1 * (cb0 * y1x + cb1 * y1y + cb2 * y1z)
            + y0 * wk4 * (vs0 * d0 + vs1 * d1 + vs2 * d2)
            + wk5 * B0v * (vs0 * y1x + vs1 * y1y + vs2 * y1z);
#pragma unroll
    for (int o = 16; o > 0; o >>= 1) t += __shfl_xor_sync(FULLMASK, t, o);
    if (lane == 0) g_logit_e[e] = t;
}

// ---------------- output: node-parallel, fused softmax + accumulate ----------------
__global__ __launch_bounds__(256) void k_out(const float* __restrict__ f,
                                             const int* __restrict__ esrc,
                                             const float* __restrict__ esh,
                                             const float* __restrict__ ecut,
                                             float* __restrict__ out) {
    __shared__ float sPart[8 * 384];
    __shared__ float sRed[16];
    const float RSQRT3 = 0.5773502691896258f;
    int tid = threadIdx.x;
    int w = tid >> 5, lane = tid & 31;
    for (int node = blockIdx.x; node < NN; node += gridDim.x) {
        int beg = g_off[node];
        int cnt = g_off[node + 1] - beg;
        // pass A: softmax stats
        float lmax = -INFINITY;
        for (int i = tid; i < cnt; i += 256) lmax = fmaxf(lmax, g_logit_e[g_perm[beg + i]]);
#pragma unroll
        for (int o = 16; o > 0; o >>= 1) lmax = fmaxf(lmax, __shfl_xor_sync(FULLMASK, lmax, o));
        if (lane == 0) sRed[w] = lmax;
        __syncthreads();
        if (tid == 0) {
            float m = sRed[0];
            for (int i = 1; i < 8; i++) m = fmaxf(m, sRed[i]);
            sRed[8] = m;
        }
        __syncthreads();
        float m = sRed[8];
        float zsum = 0.f;
        for (int i = tid; i < cnt; i += 256) zsum += expf(g_logit_e[g_perm[beg + i]] - m);
#pragma unroll
        for (int o = 16; o > 0; o >>= 1) zsum += __shfl_xor_sync(FULLMASK, zsum, o);
        if (lane == 0) sRed[w] = zsum;
        __syncthreads();
        if (tid == 0) {
            float den = 0.f;
            for (int i = 0; i < 8; i++) den += sRed[i];
            sRed[9] = den;
        }
        __syncthreads();
        float den = sRed[9];
        // pass B: accumulate
        float acc[12];
#pragma unroll
        for (int i = 0; i < 12; i++) acc[i] = 0.f;
        for (int idx = w; idx < cnt; idx += 8) {
            int e = g_perm[beg + idx];
            int src = esrc[e];
            float wv0 = g_WV[(size_t)e * 192 + lane];
            float wv1 = g_WV[(size_t)e * 192 + 32 + lane];
            float wv2 = g_WV[(size_t)e * 192 + 64 + lane];
            float wv3 = g_WV[(size_t)e * 192 + 96 + lane];
            float wv4 = g_WV[(size_t)e * 192 + 128 + lane];
            float wv5 = g_WV[(size_t)e * 192 + 160 + lane];
            const float* fs = f + (size_t)src * 160;
            float ss0 = fs[lane], ss1 = fs[32 + lane];
            float vs0 = fs[64 + 3 * lane], vs1 = fs[65 + 3 * lane], vs2 = fs[66 + 3 * lane];
            float yv = (lane < 4) ? esh[(size_t)e * 4 + lane] : 0.f;
            float y0  = __shfl_sync(FULLMASK, yv, 0);
            float y1x = __shfl_sync(FULLMASK, yv, 1);
            float y1y = __shfl_sync(FULLMASK, yv, 2);
            float y1z = __shfl_sync(FULLMASK, yv, 3);
            float z = expf(g_logit_e[e] - m);
            float alpha = z / den * ecut[e];
            float gate = sqrtf(fmaxf(alpha, 0.f) + 1e-12f);
            float gy0 = gate * y0;
            acc[0] = fmaf(gy0 * wv0, ss0, acc[0]);
            acc[1] = fmaf(gy0 * wv1, ss1, acc[1]);
            acc[2] = fmaf(gate * wv5 * RSQRT3, vs0 * y1x + vs1 * y1y + vs2 * y1z, acc[2]);
            float a1 = gate * wv2 * ss0;
            acc[3] = fmaf(a1, y1x, acc[3]); acc[4] = fmaf(a1, y1y, acc[4]); acc[5] = fmaf(a1, y1z, acc[5]);
            float a2 = gate * wv3 * ss1;
            acc[6] = fmaf(a2, y1x, acc[6]); acc[7] = fmaf(a2, y1y, acc[7]); acc[8] = fmaf(a2, y1z, acc[8]);
            float a3 = gy0 * wv4;
            acc[9] = fmaf(a3, vs0, acc[9]); acc[10] = fmaf(a3, vs1, acc[10]); acc[11] = fmaf(a3, vs2, acc[11]);
        }
        float* sp = sPart + w * 384;
        sp[lane] = acc[0];
        sp[32 + lane] = acc[1];
        sp[64 + lane] = acc[2];
        sp[96 + 3 * lane] = acc[3];  sp[97 + 3 * lane] = acc[4];  sp[98 + 3 * lane] = acc[5];
        sp[192 + 3 * lane] = acc[6]; sp[193 + 3 * lane] = acc[7]; sp[194 + 3 * lane] = acc[8];
        sp[288 + 3 * lane] = acc[9]; sp[289 + 3 * lane] = acc[10]; sp[290 + 3 * lane] = acc[11];
        __syncthreads();
        for (int ch = tid; ch < 384; ch += 256) {
            float s = 0.f;
#pragma unroll
            for (int ww = 0; ww < 8; ww++) s += sPart[ww * 384 + ch];
            out[(size_t)node * 384 + ch] = s;
        }
        __syncthreads();
    }
}

// ---------------- launch ----------------
extern "C" void kernel_launch(void* const* d_in, const int* in_sizes, int n_in,
                              void* d_out, int out_size) {
    const float* f    = (const float*)d_in[0];
    const int*   esrc = (const int*)d_in[3];
    const int*   edst = (const int*)d_in[4];
    const float* esh  = (const float*)d_in[5];
    const float* elen = (const float*)d_in[6];
    const float* ecut = (const float*)d_in[7];
    const float* Wq0  = (const float*)d_in[8];
    const float* Wq1  = (const float*)d_in[9];
    const float* Wk1  = (const float*)d_in[10];
    const float* Wk2  = (const float*)d_in[11];
    const float* Wv1  = (const float*)d_in[12];
    const float* Wv2  = (const float*)d_in[13];
    const float* Wd00a = (const float*)d_in[14];
    const float* Wd00b = (const float*)d_in[15];
    const float* Wd11a = (const float*)d_in[16];
    const float* Wd11b = (const float*)d_in[17];
    float* out = (float*)d_out;

    const int SM_NODE = 9216 * sizeof(float);
    const int SM_MLP  = (1024 + 12288 + 8192 + 1088) * sizeof(float);  // ~88.3 KB
    cudaFuncSetAttribute(k_node, cudaFuncAttributeMaxDynamicSharedMemorySize, SM_NODE);
    cudaFuncSetAttribute(k_mlp, cudaFuncAttributeMaxDynamicSharedMemorySize, SM_MLP);

    k_zero<<<(NN + 255) / 256, 256>>>();
    k_fusew<<<1, 256>>>(Wq0, Wq1, Wd00a, Wd00b, Wd11a, Wd11b);
    k_node<<<(NN + 7) / 8, 256, SM_NODE>>>(f);
    k_count<<<(EE + 255) / 256, 256>>>(edst);
    k_scan<<<1, 1024>>>();
    k_scatter<<<(EE + 255) / 256, 256>>>(edst);
    k_mlp<<<296, 256, SM_MLP>>>(elen, Wk1, Wk2, Wv1, Wv2);
    k_logit<<<EE / 8, 256>>>(f, esrc, edst, esh);
    k_out<<<2048, 256>>>(f, esrc, esh, ecut, out);
}